// round 11
// baseline (speedup 1.0000x reference)
#include <cuda_runtime.h>
#include <cuda_fp16.h>

// AdderNet 2D (K=3,S=1,P=1): out[n,f,y,x] = -sum_{c,i,j} |W[f,c,i,j] - xpad[n,c,y+i,x+j]|
// x: [8,64,32,32] f32, W: [64,64,3,3] f32, out: [8,64,32,32] f32.
//
// Identity: |w-x| = 2*max(w,x) - w - x  ->  out = Sx + Sw - 2*M
//   M  = sum max(w,x)   : HMNMX2 (alu pipe) + HADD2 (fma pipe) per pair-update
//   Sx = sum x over taps: 9 HADD2/channel (filter-independent)
//   Sw = sum w per filter: one-time prologue (shuffle reduce)
// R7 tiling: 256 CTAs (RT=4), 512 thr, 2 CTAs/SM, promote fp16->fp32 per 2 ch.

#define CIN   64
#define NFILT 64
#define HW    32
#define NIMG  8

#define FG    16
#define RT    4
#define XROWS (RT + 2)          // 6
#define XCOLS 34

#define SX_ELEMS (CIN * XROWS * XCOLS)   // 13056 halves = 26112 B
#define SW_ELEMS (CIN * 9 * FG)          // 9216 halves  = 18432 B
#define SWSUM_OFF ((SX_ELEMS + SW_ELEMS) * 2)      // 16 floats after tiles
#define SMEM_BYTES (SWSUM_OFF + 16 * 4)            // 44608 B ; sR aliases sX

__global__ __launch_bounds__(512, 2)
void adder2d_kernel(const float* __restrict__ x,
                    const float* __restrict__ W,
                    float* __restrict__ out)
{
    extern __shared__ __half smemh[];
    __half* sX  = smemh;                      // [c][r 0..5][col 0..33] fp16, zero pad
    __half* sW  = smemh + SX_ELEMS;           // [k=c*9+tap][ff 0..15]  fp16, PLAIN w
    float*  sSw = (float*)((char*)smemh + SWSUM_OFF);  // [16] filter weight sums
    float*  sR  = (float*)smemh;              // aliases after main loop: [3][17][128]

    const int tid = threadIdx.x;
    const int qtr = tid >> 7;                 // channel quarter 0..3
    const int wk  = tid & 127;                // worker = one output position
    const int yw  = wk >> 5;                  // 0..3
    const int col = wk & 31;
    const int fg  = blockIdx.x;               // 0..3
    const int rt  = blockIdx.y;               // 0..7
    const int n   = blockIdx.z;               // 0..7
    const int y0  = rt * RT;
    const int f0  = fg * FG;

    // ---- load padded x slab, fp32 -> fp16 ----
    const float* xn = x + (size_t)n * (CIN * HW * HW);
    for (int idx = tid; idx < SX_ELEMS; idx += 512) {
        int c   = idx / (XROWS * XCOLS);
        int rem = idx - c * (XROWS * XCOLS);
        int r   = rem / XCOLS;
        int cc  = rem - r * XCOLS;
        int gr  = y0 - 1 + r;
        int gc  = cc - 1;
        float v = 0.0f;
        if ((unsigned)gr < HW && (unsigned)gc < HW)
            v = xn[(c * HW + gr) * HW + gc];
        sX[idx] = __float2half_rn(v);
    }
    // ---- PLAIN fp16 weights: sW[k*16 + ff] = W[(f0+ff)*576 + k] ----
    for (int idx = tid; idx < SW_ELEMS; idx += 512) {
        int ff = idx / (CIN * 9);
        int k  = idx - ff * (CIN * 9);
        sW[k * FG + ff] = __float2half_rn(W[(f0 + ff) * (CIN * 9) + k]);
    }
    __syncthreads();

    // ---- Sw[f] = sum over 576 taps of fp16 weights (16 warps, 1 filter each) ----
    {
        const int f = tid >> 5;               // warp id = filter
        const int s = tid & 31;               // lane = 18-tap segment
        float sum = 0.0f;
#pragma unroll
        for (int e = 0; e < 18; e++)
            sum += __half2float(sW[(s * 18 + e) * FG + f]);
#pragma unroll
        for (int d = 16; d > 0; d >>= 1)
            sum += __shfl_xor_sync(0xFFFFFFFFu, sum, d);
        if (s == 0) sSw[f] = sum;
    }
    __syncthreads();

    float facc[16];                            // M accumulators (fp32)
    float fsx = 0.0f;                          // Sx accumulator (fp32)
#pragma unroll
    for (int p = 0; p < 16; p++) facc[p] = 0.0f;

    const int cbeg = qtr * (CIN / 4);
    const __half* xrow = sX + cbeg * (XROWS * XCOLS) + yw * XCOLS + col;
    const __half* wch  = sW + cbeg * 9 * FG;

#pragma unroll 1
    for (int cp = 0; cp < CIN / 8; cp++) {     // 8 pairs of channels
        __half2 hacc[8];
        __half2 hsx = __float2half2_rn(0.0f);
#pragma unroll
        for (int t = 0; t < 8; t++) hacc[t] = __float2half2_rn(0.0f);

#pragma unroll
        for (int cc = 0; cc < 2; cc++) {       // 2 channels per promote (18 taps)
#pragma unroll
            for (int i = 0; i < 3; i++) {
                __half2 xa[3];
#pragma unroll
                for (int j = 0; j < 3; j++)
                    xa[j] = __half2half2(xrow[i * XCOLS + j]);
                // Sx: both lanes duplicated, accumulate once per tap
                hsx = __hadd2(hsx, xa[0]);
                hsx = __hadd2(hsx, xa[1]);
                hsx = __hadd2(hsx, xa[2]);
#pragma unroll
                for (int j = 0; j < 3; j++) {
                    const uint4 rA = *(const uint4*)(wch + (i * 3 + j) * FG);     // f 0..7
                    const uint4 rB = *(const uint4*)(wch + (i * 3 + j) * FG + 8); // f 8..15
                    const __half2* wa = (const __half2*)&rA;
                    const __half2* wb = (const __half2*)&rB;
#pragma unroll
                    for (int q = 0; q < 4; q++) {
                        __half2 m;
                        m = __hmax2(xa[j], wa[q]);          // alu pipe (HMNMX2)
                        hacc[q]     = __hadd2(hacc[q], m);  // fma pipe
                        m = __hmax2(xa[j], wb[q]);
                        hacc[4 + q] = __hadd2(hacc[4 + q], m);
                    }
                }
            }
            xrow += XROWS * XCOLS;
            wch  += 9 * FG;
        }
        // ---- promote fp16 partials (18 taps) into fp32 ----
#pragma unroll
        for (int t = 0; t < 8; t++) {
            float2 f = __half22float2(hacc[t]);
            facc[2 * t]     += f.x;
            facc[2 * t + 1] += f.y;
        }
        fsx += __low2float(hsx);
    }

    // ---- combine 4 channel quarters (sR aliases sX, now dead) ----
    __syncthreads();
    if (qtr != 0) {
        float* buf = sR + (size_t)(qtr - 1) * (17 * 128);
#pragma unroll
        for (int p = 0; p < 16; p++) buf[p * 128 + wk] = facc[p];  // conflict-free
        buf[16 * 128 + wk] = fsx;
    }
    __syncthreads();

    if (qtr == 0) {
#pragma unroll
        for (int p = 0; p < 16; p++) {
            float s = facc[p];
#pragma unroll
            for (int r = 0; r < 3; r++)
                s += sR[(size_t)r * (17 * 128) + p * 128 + wk];
            facc[p] = s;
        }
#pragma unroll
        for (int r = 0; r < 3; r++)
            fsx += sR[(size_t)r * (17 * 128) + 16 * 128 + wk];

        // ---- write: out = Sx + Sw[f] - 2*M ;  t = g*4+q ; f = g*8+2q+lane ----
        const int gy = y0 + yw;
#pragma unroll
        for (int t = 0; t < 8; t++) {
            int g = t >> 2;
            int q = t & 3;
            int f = g * 8 + q * 2;
            float* outp = out + (((size_t)n * NFILT + f0 + f) * HW + gy) * HW + col;
            outp[0]       = fmaf(-2.0f, facc[2 * t],     fsx + sSw[f]);
            outp[HW * HW] = fmaf(-2.0f, facc[2 * t + 1], fsx + sSw[f + 1]);
        }
    }
}

extern "C" void kernel_launch(void* const* d_in, const int* in_sizes, int n_in,
                              void* d_out, int out_size)
{
    const float* x = (const float*)d_in[0];
    const float* W = (const float*)d_in[1];
    if (n_in >= 2 && in_sizes[0] == NFILT * CIN * 9 && in_sizes[1] == NIMG * CIN * HW * HW) {
        const float* t = x; x = W; W = t;
    }
    float* out = (float*)d_out;

    static int smem_set = -1;
    if (smem_set < 0) {
        cudaFuncSetAttribute(adder2d_kernel,
                             cudaFuncAttributeMaxDynamicSharedMemorySize, SMEM_BYTES);
        smem_set = 1;
    }

    dim3 grid(NFILT / FG, HW / RT, NIMG);   // 4 x 8 x 8 = 256 CTAs, 2 per SM
    adder2d_kernel<<<grid, 512, SMEM_BYTES>>>(x, W, out);
}